// round 16
// baseline (speedup 1.0000x reference)
#include <cuda_runtime.h>
#include <cuda_bf16.h>
#include <cstdint>

// CelestialWaveAggregator via per-body scalar-function tabulation.
// R8 delta (evidence-driven): round-8 ncu showed cwa_main at 32us with DRAM
// only 24.6% and issue 19.8% -- bottleneck was the LDGSTS issue rate
// (3.9M x 16B cp.async at rt=8cyc/SMSP ~= 28us of pure issue). Replaced the
// per-thread cp.async staging with cp.async.bulk (UBLKCP.S.G: ONE instruction
// per 30KB chunk, mbarrier complete_tx), 3-stage ring, 512 threads.
// R9-R15: frozen resubmits after full audits (parity/refill/alignment/tail;
// PTX ISA form verified; expect_tx ordering verified; graph-capture safe).

#define NB    13
#define NW    118
#define MAXW  12
#define NPOS  (32 * 4096)

#define NSEG   384
#define NKNOT  385
#define XMIN   (-8.0f)
#define SEG_H  (16.0f / 384.0f)
#define INV_H  24.0f

#define CHUNK   64              // positions per chunk
#define NCHUNK  (NPOS / CHUNK)  // 2048
#define MGRID   148
#define MTPB    512
#define NSTAGE  3

__constant__ int c_lens[NB]   = {9,9,9,9,9,9,9,9,9,9,12,8,3};
__constant__ int c_starts[NB] = {5,14,23,32,41,50,59,68,77,86,95,107,115};
// body ranges for 8 thread-slices: slice s handles [sbeg[s], sbeg[s+1])
__constant__ int c_sbeg[9] = {0,1,3,4,6,8,9,11,13};

__device__ float2 g_knots[NB * NKNOT];   // (f, f' * SEG_H) at each knot

// ---------------------------------------------------------------------------
__device__ __forceinline__ float gelu1(float v) {
    // exact (erf) GELU, matching jax.nn.gelu(approximate=False)
    return 0.5f * v * (1.0f + erff(v * 0.70710678118654752f));
}
__device__ __forceinline__ float gelup(float v) {
    float Phi = 0.5f * (1.0f + erff(v * 0.70710678118654752f));
    float phi = 0.3989422804014327f * __expf(-0.5f * v * v);
    return fmaf(v, phi, Phi);
}

// ---------------------------------------------------------------------------
// Kernel 1: knots (f, h*f') per (body, knot). Unchanged from R7.
__global__ __launch_bounds__(128)
void cwa_build_knots(const float* __restrict__ gW1, const float* __restrict__ gb1,
                     const float* __restrict__ gW2, const float* __restrict__ gb2,
                     const float* __restrict__ gW3, const float* __restrict__ gb3,
                     const float* __restrict__ gW4, const float* __restrict__ gb4)
{
    __shared__ float sW2T[64 * 33];
    __shared__ float sW3 [64 * 33];
    __shared__ float sW1[32], sb1[32], sb2[64], sb3[32], sW4[32];
    __shared__ float sb4;
    __shared__ float sh1 [16 * 33];
    __shared__ float sh1d[16 * 33];
    __shared__ float red [16 * 8 * 33];
    __shared__ float abuf[16 * 33];
    __shared__ float adbuf[16 * 33];

    const int c   = blockIdx.y;
    const int tid = threadIdx.x;

    for (int idx = tid; idx < 2048; idx += 128) {
        int i = idx >> 6, o = idx & 63;
        sW2T[o * 33 + i] = gW2[c * 2048 + idx];
        int o3 = idx >> 5, j = idx & 31;
        sW3[o3 * 33 + j] = gW3[c * 2048 + idx];
    }
    if (tid < 32) {
        sW1[tid] = gW1[c * 32 + tid];
        sb1[tid] = gb1[c * 32 + tid];
        sb3[tid] = gb3[c * 32 + tid];
        sW4[tid] = gW4[c * 32 + tid];
    }
    if (tid >= 64 && tid < 128) sb2[tid - 64] = gb2[c * 64 + (tid - 64)];
    if (tid == 0) sb4 = gb4[c];
    __syncthreads();

    const int p = tid >> 3;
    const int s = tid & 7;
    int kn = blockIdx.x * 16 + p;
    if (kn > NSEG) kn = NSEG;
    const float x = XMIN + SEG_H * (float)kn;

    #pragma unroll
    for (int k = 0; k < 4; k++) {
        int i = s * 4 + k;
        float v = fmaf(x, sW1[i], sb1[i]);
        sh1 [p * 33 + i] = gelu1(v);
        sh1d[p * 33 + i] = gelup(v) * sW1[i];
    }
    __syncthreads();

    float pacc[32], paccd[32];
    #pragma unroll
    for (int j = 0; j < 32; j++) { pacc[j] = 0.f; paccd[j] = 0.f; }

    for (int k = 0; k < 8; k++) {
        const int o = s * 8 + k;
        float d = sb2[o], dd = 0.f;
        #pragma unroll
        for (int i = 0; i < 32; i++) {
            float w = sW2T[o * 33 + i];
            d  = fmaf(sh1 [p * 33 + i], w, d);
            dd = fmaf(sh1d[p * 33 + i], w, dd);
        }
        const float t  = gelu1(d);
        const float td = gelup(d) * dd;
        #pragma unroll
        for (int j = 0; j < 32; j++) {
            float w = sW3[o * 33 + j];
            pacc[j]  = fmaf(t,  w, pacc[j]);
            paccd[j] = fmaf(td, w, paccd[j]);
        }
    }

    #pragma unroll
    for (int j = 0; j < 32; j++) red[(p * 8 + s) * 33 + j] = pacc[j];
    __syncthreads();
    for (int q = tid; q < 512; q += 128) {
        int p2 = q >> 5, j = q & 31;
        float a = sb3[j];
        #pragma unroll
        for (int s2 = 0; s2 < 8; s2++) a += red[(p2 * 8 + s2) * 33 + j];
        abuf[p2 * 33 + j] = a;
    }
    __syncthreads();
    #pragma unroll
    for (int j = 0; j < 32; j++) red[(p * 8 + s) * 33 + j] = paccd[j];
    __syncthreads();
    for (int q = tid; q < 512; q += 128) {
        int p2 = q >> 5, j = q & 31;
        float a = 0.f;
        #pragma unroll
        for (int s2 = 0; s2 < 8; s2++) a += red[(p2 * 8 + s2) * 33 + j];
        adbuf[p2 * 33 + j] = a;
    }
    __syncthreads();

    if (tid < 16) {
        int kn2 = blockIdx.x * 16 + tid;
        if (kn2 <= NSEG) {
            float z = sb4, zd = 0.f;
            #pragma unroll
            for (int j = 0; j < 32; j++) {
                float a  = abuf[tid * 33 + j];
                float g  = gelu1(a);
                float gd = gelup(a) * adbuf[tid * 33 + j];
                z  = fmaf(g,  sW4[j], z);
                zd = fmaf(gd, sW4[j], zd);
            }
            float f  = tanhf(z);
            float fd = (1.0f - f * f) * zd;
            g_knots[c * NKNOT + kn2] = make_float2(f, fd * SEG_H);
        }
    }
}

// ---------------------------------------------------------------------------
// Kernel 2: persistent CTAs, cp.async.bulk 3-stage mbarrier ring.
// smem floats: buf[3][7552] coef[19968] wagg[156] sout[832] mbar[6]
// total = 43618 floats = 170.4 KB (1 CTA/SM)
#define BUF_F     (CHUNK * NW)            // 7552 floats = 30208 B
#define BUF_BYTES (BUF_F * 4)
#define COEF_F    (NB * NSEG * 4)         // 19968 floats
#define OFF_COEF  (NSTAGE * BUF_F)        // 22656
#define OFF_WAGG  (OFF_COEF + COEF_F)     // 42624
#define OFF_SOUT  (OFF_WAGG + NB * MAXW)  // 42780 (16B aligned)
#define OFF_MBAR  (OFF_SOUT + CHUNK * NB) // 43612 (8B aligned)
#define SMEM_FLOATS (OFF_MBAR + 2 * NSTAGE)

__device__ __forceinline__ void mbar_init(uint32_t mbar, uint32_t count) {
    asm volatile("mbarrier.init.shared.b64 [%0], %1;" :: "r"(mbar), "r"(count) : "memory");
}
__device__ __forceinline__ void mbar_expect_tx(uint32_t mbar, uint32_t bytes) {
    asm volatile("mbarrier.arrive.expect_tx.shared.b64 _, [%0], %1;"
                 :: "r"(mbar), "r"(bytes) : "memory");
}
__device__ __forceinline__ void bulk_g2s(uint32_t dst, const void* src,
                                         uint32_t bytes, uint32_t mbar) {
    asm volatile(
        "cp.async.bulk.shared::cta.global.mbarrier::complete_tx::bytes [%0], [%1], %2, [%3];"
        :: "r"(dst), "l"(src), "r"(bytes), "r"(mbar) : "memory");
}
__device__ __forceinline__ void mbar_wait(uint32_t mbar, uint32_t parity) {
    asm volatile(
        "{\n\t"
        ".reg .pred P;\n\t"
        "WL_%=:\n\t"
        "mbarrier.try_wait.parity.acquire.cta.shared::cta.b64 P, [%0], %1, 0x989680;\n\t"
        "@P bra WD_%=;\n\t"
        "bra WL_%=;\n\t"
        "WD_%=:\n\t"
        "}"
        :: "r"(mbar), "r"(parity) : "memory");
}

__global__ __launch_bounds__(MTPB, 1)
void cwa_main(const float* __restrict__ wf,
              const float* __restrict__ gl,
              float* __restrict__ out)
{
    extern __shared__ float sm[];
    float*  wagg = sm + OFF_WAGG;
    float*  sout = sm + OFF_SOUT;
    float4* coef = (float4*)(sm + OFF_COEF);

    const int tid = threadIdx.x;
    const int bid = blockIdx.x;
    const uint32_t sbase = (uint32_t)__cvta_generic_to_shared(sm);
    const uint32_t mbar0 = sbase + OFF_MBAR * 4;

    // ---- init barriers ----
    if (tid == 0) {
        #pragma unroll
        for (int s = 0; s < NSTAGE; s++) mbar_init(mbar0 + s * 8, 1);
    }
    __syncthreads();

    // ---- prologue: fire first NSTAGE bulk copies; stage softmax + coef ----
    if (tid == 0) {
        #pragma unroll
        for (int s = 0; s < NSTAGE; s++) {
            const int ch = bid + s * MGRID;
            if (ch < NCHUNK) {
                mbar_expect_tx(mbar0 + s * 8, BUF_BYTES);
                bulk_g2s(sbase + s * BUF_BYTES, wf + (size_t)ch * BUF_F,
                         BUF_BYTES, mbar0 + s * 8);
            }
        }
    }

    // per-body ragged softmax
    if (tid < NB) {
        const int len = c_lens[tid];
        float v[MAXW];
        float mx = -1e30f;
        for (int j = 0; j < len; j++) { v[j] = gl[tid * MAXW + j]; mx = fmaxf(mx, v[j]); }
        float ssum = 0.f;
        for (int j = 0; j < len; j++) { v[j] = expf(v[j] - mx); ssum += v[j]; }
        const float inv = 1.0f / ssum;
        for (int j = 0; j < MAXW; j++) wagg[tid * MAXW + j] = (j < len) ? v[j] * inv : 0.f;
    }

    // knots -> cubic Hermite coefficients per (body, segment)
    {
        const float2* __restrict__ kn = g_knots;
        for (int seg = tid; seg < NB * NSEG; seg += MTPB) {
            const int c = seg / NSEG, i = seg - c * NSEG;
            const float2 k0 = __ldg(kn + c * NKNOT + i);
            const float2 k1 = __ldg(kn + c * NKNOT + i + 1);
            const float c2 = fmaf(3.0f, k1.x - k0.x, -2.0f * k0.y - k1.y);
            const float c3 = fmaf(2.0f, k0.x - k1.x,  k0.y + k1.y);
            coef[seg] = make_float4(k0.x, k0.y, c2, c3);
        }
    }
    __syncthreads();   // wagg/coef visible to all before first compute

    // ---- main pipeline ----
    const int slice = tid & 7;            // 8 body-slices
    const int pos   = tid >> 3;           // 64 positions
    const int cbeg  = c_sbeg[slice];
    const int cend  = c_sbeg[slice + 1];

    for (int m = 0; ; m++) {
        const int ch = bid + m * MGRID;
        if (ch >= NCHUNK) break;
        const int slot = m % NSTAGE;
        const uint32_t mb = mbar0 + slot * 8;

        mbar_wait(mb, (m / NSTAGE) & 1);

        const float* row = sm + slot * BUF_F + pos * NW;
        for (int c = cbeg; c < cend; c++) {
            const int st = c_starts[c], ln = c_lens[c];
            float x = 0.f;
            for (int j = 0; j < ln; j++)
                x = fmaf(wagg[c * MAXW + j], row[st + j], x);
            float u = (x - XMIN) * INV_H;
            u = fminf(fmaxf(u, 0.0f), 383.999f);
            const int   i = (int)u;
            const float t = u - (float)i;
            const float4 cv = coef[c * NSEG + i];
            sout[pos * NB + c] =
                fmaf(fmaf(fmaf(cv.w, t, cv.z), t, cv.y), t, cv.x);
        }
        __syncthreads();   // all reads of buf[slot] + writes of sout complete

        // refill this slot with chunk m+NSTAGE (safe: all readers past barrier)
        if (tid == 0) {
            const int chn = ch + NSTAGE * MGRID;
            if (chn < NCHUNK) {
                mbar_expect_tx(mb, BUF_BYTES);
                bulk_g2s(sbase + slot * BUF_BYTES, wf + (size_t)chn * BUF_F,
                         BUF_BYTES, mb);
            }
        }

        // coalesced store of this chunk's 64*13 outputs
        {
            const float4* so4 = (const float4*)sout;
            float4* ob4 = (float4*)(out + (size_t)ch * (CHUNK * NB));
            if (tid < (CHUNK * NB) / 4) ob4[tid] = so4[tid];
        }
        __syncthreads();   // sout store-reads done before next iteration writes
    }
}

// ---------------------------------------------------------------------------
extern "C" void kernel_launch(void* const* d_in, const int* in_sizes, int n_in,
                              void* d_out, int out_size)
{
    (void)in_sizes; (void)n_in; (void)out_size;
    const float* wf  = (const float*)d_in[0];
    const float* gl  = (const float*)d_in[1];
    const float* gW1 = (const float*)d_in[2];
    const float* gb1 = (const float*)d_in[3];
    const float* gW2 = (const float*)d_in[4];
    const float* gb2 = (const float*)d_in[5];
    const float* gW3 = (const float*)d_in[6];
    const float* gb3 = (const float*)d_in[7];
    const float* gW4 = (const float*)d_in[8];
    const float* gb4 = (const float*)d_in[9];
    float* out = (float*)d_out;

    // Idempotent, not a stream op (not captured); called every launch.
    cudaFuncSetAttribute(cwa_main,
                         cudaFuncAttributeMaxDynamicSharedMemorySize,
                         SMEM_FLOATS * 4);

    dim3 bgrid((NKNOT + 15) / 16, NB);
    cwa_build_knots<<<bgrid, 128>>>(gW1, gb1, gW2, gb2, gW3, gb3, gW4, gb4);

    cwa_main<<<MGRID, MTPB, SMEM_FLOATS * 4>>>(wf, gl, out);
}